// round 15
// baseline (speedup 1.0000x reference)
#include <cuda_runtime.h>
#include <cuda_fp16.h>
#include <math.h>
#include <stdint.h>

// Problem constants
#define C_CH 8
#define F_DIM 1024
#define W_FR 512
#define H_HEADS 16
#define D_HEAD 64
#define F4 4096

// ---------------------------------------------------------------------------
// Scratch (weights consumed fp32 directly -> conversion buffers removed)
// ---------------------------------------------------------------------------
__device__ __align__(16) __half g_ph[C_CH * F_DIM * W_FR];        // 8 MB  projection fp16
__device__ __align__(16) __half g_t1h[C_CH * W_FR * F_DIM];       // 8 MB  acts^T fp16
__device__ __align__(16) __half g_t2h[(size_t)C_CH * W_FR * F4];  // 32 MB hidden^T fp16

// ---------------------------------------------------------------------------
// helpers
// ---------------------------------------------------------------------------
__device__ __forceinline__ uint32_t smem_u32(const void* p) {
    uint32_t a;
    asm("{ .reg .u64 t; cvta.to.shared.u64 t, %1; cvt.u32.u64 %0, t; }" : "=r"(a) : "l"(p));
    return a;
}
__device__ __forceinline__ void cp16s(uint32_t dst, const void* src) {
    asm volatile("cp.async.ca.shared.global [%0], [%1], 16;" :: "r"(dst), "l"(src));
}
__device__ __forceinline__ void mma_f16(float* c, const uint32_t* a, const uint32_t* b) {
    asm volatile(
        "mma.sync.aligned.m16n8k16.row.col.f32.f16.f16.f32 "
        "{%0,%1,%2,%3}, {%4,%5,%6,%7}, {%8,%9}, {%0,%1,%2,%3};"
        : "+f"(c[0]), "+f"(c[1]), "+f"(c[2]), "+f"(c[3])
        : "r"(a[0]), "r"(a[1]), "r"(a[2]), "r"(a[3]), "r"(b[0]), "r"(b[1]));
}
__device__ __forceinline__ void ldsm4(uint32_t* r, uint32_t addr) {
    asm volatile("ldmatrix.sync.aligned.m8n8.x4.shared.b16 {%0,%1,%2,%3}, [%4];"
        : "=r"(r[0]), "=r"(r[1]), "=r"(r[2]), "=r"(r[3]) : "r"(addr));
}
__device__ __forceinline__ float gelu_exact(float v) {
    return 0.5f * v * (1.f + erff(v * 0.70710678118654752f));
}

// ---------------------------------------------------------------------------
// Fused frame-norm + transpose + fp16 convert:
// out_h[c][w][f] = (half) normalize(in[c][f][w]).
// grid (C, W/32), block 256 = (8 f-groups) x (32 w-lanes).
// ---------------------------------------------------------------------------
__global__ __launch_bounds__(256) void norm_t_kernel(
    const float* __restrict__ in, const float* __restrict__ gw,
    const float* __restrict__ bw, __half* __restrict__ outT)
{
    int c  = blockIdx.x;
    int w0 = blockIdx.y * 32;
    int wx = threadIdx.x & 31;
    int fg = threadIdx.x >> 5;
    const float* base = in + ((size_t)c * F_DIM) * W_FR + w0 + wx;

    float s = 0.f, ss = 0.f;
    for (int f = fg; f < F_DIM; f += 8) {
        float v = base[(size_t)f * W_FR];
        s += v; ss += v * v;
    }
    __shared__ float red[2][8][32];
    __shared__ float smu[32], srs[32];
    __shared__ __half tile[32][34];
    red[0][fg][wx] = s; red[1][fg][wx] = ss;
    __syncthreads();
    if (fg == 0) {
        float S = 0.f, SS = 0.f;
#pragma unroll
        for (int i = 0; i < 8; i++) { S += red[0][i][wx]; SS += red[1][i][wx]; }
        float mu  = S * (1.0f / F_DIM);
        float var = SS * (1.0f / F_DIM) - mu * mu;
        smu[wx] = mu;
        srs[wx] = rsqrtf(var + 1e-5f);
    }
    __syncthreads();
    float mu = smu[wx], rs = srs[wx];

    int rr = threadIdx.x >> 3;          // 0..31: local w row for write-out
    int cc = (threadIdx.x & 7) * 4;     // 0..28: f col chunk
    __half* ob = outT + ((size_t)c * W_FR + w0 + rr) * F_DIM;

    for (int ft = 0; ft < F_DIM / 32; ft++) {
#pragma unroll
        for (int j = 0; j < 4; j++) {
            int fl = fg * 4 + j;
            int f  = ft * 32 + fl;
            float v = base[(size_t)f * W_FR];
            tile[fl][wx] = __float2half((v - mu) * rs * gw[f] + bw[f]);
        }
        __syncthreads();
        __half2 p0 = __halves2half2(tile[cc][rr],     tile[cc + 1][rr]);
        __half2 p1 = __halves2half2(tile[cc + 2][rr], tile[cc + 3][rr]);
        *(__half2*)(ob + ft * 32 + cc)     = p0;
        *(__half2*)(ob + ft * 32 + cc + 2) = p1;
        __syncthreads();
    }
}

// ---------------------------------------------------------------------------
// FP16 tensor-core batched GEMM, v2 body, A consumed as FP32 (LDG+cvt+STS,
// register double buffer); B fp16 via 4-stage cp.async. 256 thr, 8 warps
// (2m x 4n), warp tile 64x32, CTA tile 128x128, BK=32, ldmatrix, 2 CTAs/SM.
// C[c][M,512] = A[c][M,K](fp32) x BT[c][512,K](fp16). Rows padded HP=40.
// epi: 1 = GELU + fp16 + TRANSPOSED store (Cout[n][M]),
//      2 = fp32 residual-add store, 3 = fp16 store
// ---------------------------------------------------------------------------
#define BK2 32
#define HP 40
#define NSTG 4
#define A_MAT (128 * HP)                        // halves per A buffer
#define HG_SMEM ((2 * A_MAT + NSTG * A_MAT) * 2)   // 61,440 B

__global__ __launch_bounds__(256, 2) void hgemm_kernel(
    const float* __restrict__ A, const __half* __restrict__ BT,
    void* __restrict__ Cout, const float* __restrict__ R,
    int M, int K, int epi)
{
    const int N = W_FR;
    int c  = blockIdx.z;
    int bm = blockIdx.y * 128;
    int bn = blockIdx.x * 128;
    A  += (size_t)c * M * K;
    BT += (size_t)c * N * K;
    float*  Cf = (float*)Cout + (size_t)c * M * N;
    __half* Ch = (__half*)Cout + (size_t)c * M * N;   // epi 3
    __half* Ct = (__half*)Cout + (size_t)c * N * M;   // epi 1 (transposed out)
    if (R) R += (size_t)c * M * N;

    extern __shared__ __align__(16) __half hsm[];
    uint32_t smb = smem_u32(hsm);
    const uint32_t bsOff = (uint32_t)(2 * A_MAT) * 2;   // byte offset of B stages

    int tid  = threadIdx.x;
    int warp = tid >> 5;
    int lane = tid & 31;
    int gid  = lane >> 2;
    int tig  = lane & 3;
    int wm   = warp >> 2;
    int wn   = warp & 3;

    // copy assignment: row = tid>>1, 16-col chunk = (tid&1)*16
    int cr = tid >> 1;
    int cc = (tid & 1) * 16;
    const float*  Ag = A  + (size_t)(bm + cr) * K + cc;
    const __half* Bg = BT + (size_t)(bn + cr) * K + cc;
    uint32_t sdst = (uint32_t)(cr * HP + cc) * 2;       // bytes within buffer

    // ldmatrix per-lane offsets
    int lr = lane & 7;
    int lm = (lane >> 3) & 1;
    int lc = (lane >> 4) & 1;
    uint32_t aoff = (uint32_t)((wm * 64 + lr + lm * 8) * HP + lc * 8) * 2;
    uint32_t boff = (uint32_t)((wn * 32 + lr + lc * 8) * HP + lm * 8) * 2;

    const int NT = K / BK2;

    float ar[16];
    // A tile 0 -> regs -> As[0]
#pragma unroll
    for (int j = 0; j < 4; j++)
        *(float4*)&ar[j * 4] = *(const float4*)(Ag + j * 4);
    {
        uint32_t d = smb + sdst;
#pragma unroll
        for (int j = 0; j < 8; j++) {
            __half2 hv = __floats2half2_rn(ar[2 * j], ar[2 * j + 1]);
            *(__half2*)((char*)hsm + (d - smb) + j * 4) = hv;
        }
    }
    // A tile 1 -> regs (held)
#pragma unroll
    for (int j = 0; j < 4; j++)
        *(float4*)&ar[j * 4] = *(const float4*)(Ag + BK2 + j * 4);

    // B stages 0..2
#pragma unroll
    for (int t = 0; t < NSTG - 1; t++) {
        uint32_t sB = smb + bsOff + (uint32_t)(t * A_MAT) * 2;
        cp16s(sB + sdst,      Bg + (size_t)t * BK2);
        cp16s(sB + sdst + 16, Bg + (size_t)t * BK2 + 8);
        asm volatile("cp.async.commit_group;");
    }

    float acc[4][4][4];
#pragma unroll
    for (int i = 0; i < 4; i++)
#pragma unroll
        for (int j = 0; j < 4; j++)
#pragma unroll
            for (int q = 0; q < 4; q++) acc[i][j][q] = 0.f;

    for (int t = 0; t < NT; t++) {
        uint32_t sA = smb + (uint32_t)((t & 1) * A_MAT) * 2;
        uint32_t sB = smb + bsOff + (uint32_t)((t % NSTG) * A_MAT) * 2;
        asm volatile("cp.async.wait_group %0;" :: "n"(NSTG - 2));
        __syncthreads();

#pragma unroll
        for (int s = 0; s < 2; s++) {
            uint32_t bf[2][4];
            ldsm4(bf[0], sB + boff + (0 * 16 * HP + s * 16) * 2);
            ldsm4(bf[1], sB + boff + (1 * 16 * HP + s * 16) * 2);
#pragma unroll
            for (int mt = 0; mt < 4; mt++) {
                uint32_t af[4];
                ldsm4(af, sA + aoff + (mt * 16 * HP + s * 16) * 2);
                mma_f16(acc[mt][0], af, &bf[0][0]);
                mma_f16(acc[mt][1], af, &bf[0][2]);
                mma_f16(acc[mt][2], af, &bf[1][0]);
                mma_f16(acc[mt][3], af, &bf[1][2]);
            }
        }

        // store A tile t+1 (in regs) into the buffer NOT read this iter
        if (t + 1 < NT) {
            char* d = (char*)hsm + ((t + 1) & 1) * A_MAT * 2 + sdst;
#pragma unroll
            for (int j = 0; j < 8; j++)
                *(__half2*)(d + j * 4) = __floats2half2_rn(ar[2 * j], ar[2 * j + 1]);
        }
        // load A tile t+2 into regs
        if (t + 2 < NT) {
            const float* Ap = Ag + (size_t)(t + 2) * BK2;
#pragma unroll
            for (int j = 0; j < 4; j++)
                *(float4*)&ar[j * 4] = *(const float4*)(Ap + j * 4);
        }
        // issue B tile t+3
        if (t + NSTG - 1 < NT) {
            int tn = t + NSTG - 1;
            uint32_t dB = smb + bsOff + (uint32_t)((tn % NSTG) * A_MAT) * 2;
            cp16s(dB + sdst,      Bg + (size_t)tn * BK2);
            cp16s(dB + sdst + 16, Bg + (size_t)tn * BK2 + 8);
        }
        asm volatile("cp.async.commit_group;");
    }

    if (epi == 1) {
        // GELU + fp16 + transpose via smem, store Ct[n][M]
        asm volatile("cp.async.wait_group 0;");
        __syncthreads();
        __half* ts = hsm;                     // [128 n][136 m]
#pragma unroll
        for (int mt = 0; mt < 4; mt++)
#pragma unroll
            for (int nt = 0; nt < 4; nt++)
#pragma unroll
                for (int q = 0; q < 4; q++) {
                    int row = wm * 64 + mt * 16 + gid + (q >> 1) * 8;
                    int col = wn * 32 + nt * 8 + 2 * tig + (q & 1);
                    ts[col * 136 + row] = __float2half(gelu_exact(acc[mt][nt][q]));
                }
        __syncthreads();
#pragma unroll
        for (int pp = 0; pp < 8; pp++) {
            int nr  = pp * 16 + (tid >> 4);
            int c16 = (tid & 15) * 8;
            uint4 v = *(const uint4*)&ts[nr * 136 + c16];
            *(uint4*)&Ct[(size_t)(bn + nr) * M + bm + c16] = v;
        }
        return;
    }

#pragma unroll
    for (int mt = 0; mt < 4; mt++) {
#pragma unroll
        for (int nt = 0; nt < 4; nt++) {
            int row0 = bm + wm * 64 + mt * 16 + gid;
            int col  = bn + wn * 32 + nt * 8 + 2 * tig;
#pragma unroll
            for (int h = 0; h < 2; h++) {
                int row = row0 + h * 8;
                float2 v = make_float2(acc[mt][nt][h * 2], acc[mt][nt][h * 2 + 1]);
                size_t off = (size_t)row * N + col;
                if (epi == 3) {
                    *(__half2*)(Ch + off) = __floats2half2_rn(v.x, v.y);
                } else {
                    float2 rv = *(const float2*)(R + off);
                    v.x += rv.x; v.y += rv.y;
                    *(float2*)(Cf + off) = v;
                }
            }
        }
    }
}

// ---------------------------------------------------------------------------
// Flash attention, fp16 mma. Reads fp16 projection p[d][w]; writes output
// DIRECTLY to t1h fp16 transposed ([w][f] layout). Grid 256, 256 thr.
// ---------------------------------------------------------------------------
#define AQS 72
#define AVS 520
#define ATT_SMEM (512 * AQS * 2 + 64 * AVS * 2)   // 140,288 B

__global__ __launch_bounds__(256) void fattn_kernel(
    const __half* __restrict__ ph, const float* __restrict__ freqs,
    __half* __restrict__ t1)
{
    extern __shared__ __align__(16) char smraw[];
    __half* qk = (__half*)smraw;
    __half* vs = (__half*)(smraw + 512 * AQS * 2);

    int head = blockIdx.x >> 1;
    int qh   = blockIdx.x & 1;
    int c  = head >> 4;
    int hh = head & 15;
    const __half* slab = ph + ((size_t)c * F_DIM + (size_t)hh * D_HEAD) * W_FR;

    int tid = threadIdx.x;

#pragma unroll
    for (int rep = 0; rep < 2; rep++) {
        int w = tid + rep * 256;
        float fw = (float)w;
#pragma unroll
        for (int i = 0; i < 16; i++) {
            float e0 = __half2float(slab[(size_t)(2 * i) * W_FR + w]);
            float e1 = __half2float(slab[(size_t)(2 * i + 1) * W_FR + w]);
            float si, co;
            sincosf(fw * freqs[i], &si, &co);
            qk[w * AQS + 2 * i]     = __float2half(e0 * co - e1 * si);
            qk[w * AQS + 2 * i + 1] = __float2half(e1 * co + e0 * si);
            vs[(2 * i) * AVS + w]     = __float2half(e0);
            vs[(2 * i + 1) * AVS + w] = __float2half(e1);
        }
#pragma unroll
        for (int d = 32; d < 64; d++) {
            __half he = slab[(size_t)d * W_FR + w];
            qk[w * AQS + d] = he;
            vs[d * AVS + w] = he;
        }
    }
    __syncthreads();

    int warp = tid >> 5, lane = tid & 31, gid = lane >> 2, tig = lane & 3;
    int q0 = qh * 256 + warp * 32;
    const float scale = 0.03125f;

    uint32_t qf[2][4][4];
#pragma unroll
    for (int mt = 0; mt < 2; mt++) {
        int qr = q0 + mt * 16 + gid;
#pragma unroll
        for (int ks = 0; ks < 4; ks++) {
            int kb = 16 * ks + 2 * tig;
            qf[mt][ks][0] = *(const uint32_t*)&qk[qr * AQS + kb];
            qf[mt][ks][1] = *(const uint32_t*)&qk[(qr + 8) * AQS + kb];
            qf[mt][ks][2] = *(const uint32_t*)&qk[qr * AQS + kb + 8];
            qf[mt][ks][3] = *(const uint32_t*)&qk[(qr + 8) * AQS + kb + 8];
        }
    }

    float oacc[2][8][4];
#pragma unroll
    for (int mt = 0; mt < 2; mt++)
#pragma unroll
        for (int nt = 0; nt < 8; nt++)
#pragma unroll
            for (int q = 0; q < 4; q++) oacc[mt][nt][q] = 0.f;
    float mrow[2][2] = { {-1e30f, -1e30f}, {-1e30f, -1e30f} };
    float lrow[2][2] = { {0.f, 0.f}, {0.f, 0.f} };

    for (int ch = 0; ch < 8; ch++) {
        int cb = ch * 64;
        float sacc[2][8][4];
#pragma unroll
        for (int mt = 0; mt < 2; mt++)
#pragma unroll
            for (int nt = 0; nt < 8; nt++)
#pragma unroll
                for (int q = 0; q < 4; q++) sacc[mt][nt][q] = 0.f;

#pragma unroll
        for (int ks = 0; ks < 4; ks++) {
#pragma unroll
            for (int nt = 0; nt < 8; nt++) {
                int kr = cb + nt * 8 + gid;
                uint32_t bf[2];
                int kb = 16 * ks + 2 * tig;
                bf[0] = *(const uint32_t*)&qk[kr * AQS + kb];
                bf[1] = *(const uint32_t*)&qk[kr * AQS + kb + 8];
                mma_f16(sacc[0][nt], qf[0][ks], bf);
                mma_f16(sacc[1][nt], qf[1][ks], bf);
            }
        }

#pragma unroll
        for (int mt = 0; mt < 2; mt++) {
#pragma unroll
            for (int h = 0; h < 2; h++) {
                float mx = -1e30f;
#pragma unroll
                for (int nt = 0; nt < 8; nt++) {
                    mx = fmaxf(mx, sacc[mt][nt][h * 2]);
                    mx = fmaxf(mx, sacc[mt][nt][h * 2 + 1]);
                }
                mx *= scale;
                mx = fmaxf(mx, __shfl_xor_sync(0xFFFFFFFF, mx, 1));
                mx = fmaxf(mx, __shfl_xor_sync(0xFFFFFFFF, mx, 2));
                float newm = fmaxf(mrow[mt][h], mx);
                float scl  = __expf(mrow[mt][h] - newm);
                float rsum = 0.f;
#pragma unroll
                for (int nt = 0; nt < 8; nt++) {
                    float e0 = __expf(sacc[mt][nt][h * 2] * scale - newm);
                    float e1 = __expf(sacc[mt][nt][h * 2 + 1] * scale - newm);
                    sacc[mt][nt][h * 2]     = e0;
                    sacc[mt][nt][h * 2 + 1] = e1;
                    rsum += e0 + e1;
                }
                rsum += __shfl_xor_sync(0xFFFFFFFF, rsum, 1);
                rsum += __shfl_xor_sync(0xFFFFFFFF, rsum, 2);
                lrow[mt][h] = lrow[mt][h] * scl + rsum;
                mrow[mt][h] = newm;
#pragma unroll
                for (int nt = 0; nt < 8; nt++) {
                    oacc[mt][nt][h * 2]     *= scl;
                    oacc[mt][nt][h * 2 + 1] *= scl;
                }
            }
        }

#pragma unroll
        for (int ks = 0; ks < 4; ks++) {
            uint32_t pf[2][4];
#pragma unroll
            for (int mt = 0; mt < 2; mt++) {
                __half2 h0 = __floats2half2_rn(sacc[mt][2 * ks][0],     sacc[mt][2 * ks][1]);
                __half2 h1 = __floats2half2_rn(sacc[mt][2 * ks][2],     sacc[mt][2 * ks][3]);
                __half2 h2 = __floats2half2_rn(sacc[mt][2 * ks + 1][0], sacc[mt][2 * ks + 1][1]);
                __half2 h3 = __floats2half2_rn(sacc[mt][2 * ks + 1][2], sacc[mt][2 * ks + 1][3]);
                pf[mt][0] = *(uint32_t*)&h0;
                pf[mt][1] = *(uint32_t*)&h1;
                pf[mt][2] = *(uint32_t*)&h2;
                pf[mt][3] = *(uint32_t*)&h3;
            }
#pragma unroll
            for (int dnt = 0; dnt < 8; dnt++) {
                int vr = dnt * 8 + gid;
                uint32_t vf[2];
                int kcol = cb + 16 * ks + 2 * tig;
                vf[0] = *(const uint32_t*)&vs[vr * AVS + kcol];
                vf[1] = *(const uint32_t*)&vs[vr * AVS + kcol + 8];
                mma_f16(oacc[0][dnt], pf[0], vf);
                mma_f16(oacc[1][dnt], pf[1], vf);
            }
        }
    }

    // direct fp16 transposed output into t1h[w][f]
    __half* tout = t1 + ((size_t)c * W_FR + qh * 256) * F_DIM + hh * D_HEAD;
#pragma unroll
    for (int mt = 0; mt < 2; mt++)
#pragma unroll
        for (int dnt = 0; dnt < 8; dnt++)
#pragma unroll
            for (int h = 0; h < 2; h++) {
                int row = warp * 32 + mt * 16 + gid + h * 8;
                int d2  = dnt * 8 + 2 * tig;
                float li = 1.f / lrow[mt][h];
                *(__half2*)(tout + (size_t)row * F_DIM + d2) =
                    __floats2half2_rn(oacc[mt][dnt][h * 2] * li,
                                      oacc[mt][dnt][h * 2 + 1] * li);
            }
}

// ---------------------------------------------------------------------------
// Launch
// ---------------------------------------------------------------------------
extern "C" void kernel_launch(void* const* d_in, const int* in_sizes, int n_in,
                              void* d_out, int out_size)
{
    (void)in_sizes; (void)n_in; (void)out_size;
    const float* x  = (const float*)d_in[0];
    const float* g1 = (const float*)d_in[1];
    const float* b1 = (const float*)d_in[2];
    const float* wq = (const float*)d_in[3];
    const float* wo = (const float*)d_in[4];
    const float* fr = (const float*)d_in[5];
    const float* g2 = (const float*)d_in[6];
    const float* b2 = (const float*)d_in[7];
    const float* w1 = (const float*)d_in[8];
    const float* w2 = (const float*)d_in[9];
    float* out = (float*)d_out;

    __half *ph, *t1h, *t2h;
    cudaGetSymbolAddress((void**)&ph,  g_ph);
    cudaGetSymbolAddress((void**)&t1h, g_t1h);
    cudaGetSymbolAddress((void**)&t2h, g_t2h);

    cudaFuncSetAttribute(fattn_kernel,
                         cudaFuncAttributeMaxDynamicSharedMemorySize, ATT_SMEM);
    cudaFuncSetAttribute(hgemm_kernel,
                         cudaFuncAttributeMaxDynamicSharedMemorySize, HG_SMEM);

    // t1h = (half) norm(x)^T
    norm_t_kernel<<<dim3(8, 16), 256>>>(x, g1, b1, t1h);
    // ph (fp16) = w_q @ z
    hgemm_kernel<<<dim3(4, 8, 8), 256, HG_SMEM>>>(wq, t1h, ph, nullptr, F_DIM, F_DIM, 3);
    // t1h = attention(ph)^T (fp16, direct)
    fattn_kernel<<<256, 256, ATT_SMEM>>>(ph, fr, t1h);
    // out = x + w_o @ o
    hgemm_kernel<<<dim3(4, 8, 8), 256, HG_SMEM>>>(wo, t1h, out, x, F_DIM, F_DIM, 2);
    // t1h = (half) norm(out)^T
    norm_t_kernel<<<dim3(8, 16), 256>>>(out, g2, b2, t1h);
    // t2h = (gelu(w1 @ z))^T  (fp16, in-epilogue transpose)
    hgemm_kernel<<<dim3(4, 32, 8), 256, HG_SMEM>>>(w1, t1h, t2h, nullptr, F4, F_DIM, 1);
    // out = out + w2 @ h
    hgemm_kernel<<<dim3(4, 8, 8), 256, HG_SMEM>>>(w2, t2h, out, out, F_DIM, F4, 2);
}

// round 16
// speedup vs baseline: 1.0653x; 1.0653x over previous
#include <cuda_runtime.h>
#include <cuda_fp16.h>
#include <math.h>
#include <stdint.h>

// Problem constants
#define C_CH 8
#define F_DIM 1024
#define W_FR 512
#define H_HEADS 16
#define D_HEAD 64
#define F4 4096

// ---------------------------------------------------------------------------
// Scratch
// ---------------------------------------------------------------------------
__device__ __align__(16) __half g_ph[C_CH * F_DIM * W_FR];        // 8 MB  projection fp16
__device__ __align__(16) __half g_wqh[C_CH * F_DIM * F_DIM];      // 16 MB
__device__ __align__(16) __half g_woh[C_CH * F_DIM * F_DIM];      // 16 MB
__device__ __align__(16) __half g_w1h[(size_t)C_CH * F4 * F_DIM]; // 64 MB
__device__ __align__(16) __half g_w2h[(size_t)C_CH * F_DIM * F4]; // 64 MB
__device__ __align__(16) __half g_t1h[C_CH * W_FR * F_DIM];       // 8 MB  acts^T fp16
__device__ __align__(16) __half g_t2h[(size_t)C_CH * W_FR * F4];  // 32 MB hidden^T fp16

// ---------------------------------------------------------------------------
// helpers
// ---------------------------------------------------------------------------
__device__ __forceinline__ uint32_t smem_u32(const void* p) {
    uint32_t a;
    asm("{ .reg .u64 t; cvta.to.shared.u64 t, %1; cvt.u32.u64 %0, t; }" : "=r"(a) : "l"(p));
    return a;
}
__device__ __forceinline__ void cp16s(uint32_t dst, const void* src) {
    asm volatile("cp.async.ca.shared.global [%0], [%1], 16;" :: "r"(dst), "l"(src));
}
__device__ __forceinline__ void mma_f16(float* c, const uint32_t* a, const uint32_t* b) {
    asm volatile(
        "mma.sync.aligned.m16n8k16.row.col.f32.f16.f16.f32 "
        "{%0,%1,%2,%3}, {%4,%5,%6,%7}, {%8,%9}, {%0,%1,%2,%3};"
        : "+f"(c[0]), "+f"(c[1]), "+f"(c[2]), "+f"(c[3])
        : "r"(a[0]), "r"(a[1]), "r"(a[2]), "r"(a[3]), "r"(b[0]), "r"(b[1]));
}
__device__ __forceinline__ void ldsm4(uint32_t* r, uint32_t addr) {
    asm volatile("ldmatrix.sync.aligned.m8n8.x4.shared.b16 {%0,%1,%2,%3}, [%4];"
        : "=r"(r[0]), "=r"(r[1]), "=r"(r[2]), "=r"(r[3]) : "r"(addr));
}
__device__ __forceinline__ float gelu_exact(float v) {
    return 0.5f * v * (1.f + erff(v * 0.70710678118654752f));
}

// ---------------------------------------------------------------------------
// fp32 -> fp16 elementwise (weights)
// ---------------------------------------------------------------------------
__global__ __launch_bounds__(256) void f2h_kernel(
    const float* __restrict__ in, __half* __restrict__ out, size_t n)
{
    size_t i = ((size_t)blockIdx.x * blockDim.x + threadIdx.x) * 4;
    if (i >= n) return;
    float4 v = *(const float4*)(in + i);
    *(__half2*)(out + i)     = __floats2half2_rn(v.x, v.y);
    *(__half2*)(out + i + 2) = __floats2half2_rn(v.z, v.w);
}

// ---------------------------------------------------------------------------
// Fused frame-norm + transpose + fp16 convert:
// out_h[c][w][f] = (half) normalize(in[c][f][w]).
// grid (C, W/32), block 256 = (8 f-groups) x (32 w-lanes).
// ---------------------------------------------------------------------------
__global__ __launch_bounds__(256) void norm_t_kernel(
    const float* __restrict__ in, const float* __restrict__ gw,
    const float* __restrict__ bw, __half* __restrict__ outT)
{
    int c  = blockIdx.x;
    int w0 = blockIdx.y * 32;
    int wx = threadIdx.x & 31;
    int fg = threadIdx.x >> 5;
    const float* base = in + ((size_t)c * F_DIM) * W_FR + w0 + wx;

    float s = 0.f, ss = 0.f;
    for (int f = fg; f < F_DIM; f += 8) {
        float v = base[(size_t)f * W_FR];
        s += v; ss += v * v;
    }
    __shared__ float red[2][8][32];
    __shared__ float smu[32], srs[32];
    __shared__ __half tile[32][34];
    red[0][fg][wx] = s; red[1][fg][wx] = ss;
    __syncthreads();
    if (fg == 0) {
        float S = 0.f, SS = 0.f;
#pragma unroll
        for (int i = 0; i < 8; i++) { S += red[0][i][wx]; SS += red[1][i][wx]; }
        float mu  = S * (1.0f / F_DIM);
        float var = SS * (1.0f / F_DIM) - mu * mu;
        smu[wx] = mu;
        srs[wx] = rsqrtf(var + 1e-5f);
    }
    __syncthreads();
    float mu = smu[wx], rs = srs[wx];

    int rr = threadIdx.x >> 3;          // 0..31: local w row for write-out
    int cc = (threadIdx.x & 7) * 4;     // 0..28: f col chunk
    __half* ob = outT + ((size_t)c * W_FR + w0 + rr) * F_DIM;

    for (int ft = 0; ft < F_DIM / 32; ft++) {
#pragma unroll
        for (int j = 0; j < 4; j++) {
            int fl = fg * 4 + j;
            int f  = ft * 32 + fl;
            float v = base[(size_t)f * W_FR];
            tile[fl][wx] = __float2half((v - mu) * rs * gw[f] + bw[f]);
        }
        __syncthreads();
        __half2 p0 = __halves2half2(tile[cc][rr],     tile[cc + 1][rr]);
        __half2 p1 = __halves2half2(tile[cc + 2][rr], tile[cc + 3][rr]);
        *(__half2*)(ob + ft * 32 + cc)     = p0;
        *(__half2*)(ob + ft * 32 + cc + 2) = p1;
        __syncthreads();
    }
}

// ---------------------------------------------------------------------------
// FP16 tensor-core batched GEMM (R14 body): 256 thr, 8 warps (2m x 4n),
// warp tile 64x32, CTA tile 128x128, BK=32, ldmatrix, 4-stage cp.async,
// 2 CTAs/SM. Rows padded HP=40.
// epi: 1 = GELU + fp16 + TRANSPOSED store (Cout[n][M]),
//      2 = fp32 residual-add store, 3 = fp16 store
// ---------------------------------------------------------------------------
#define BK2 32
#define HP 40
#define NSTG 4
#define HG_MAT (128 * HP)                      // halves per matrix per stage
#define HG_SMEM (NSTG * 2 * HG_MAT * 2)        // 81,920 B

__global__ __launch_bounds__(256, 2) void hgemm_kernel(
    const __half* __restrict__ A, const __half* __restrict__ BT,
    void* __restrict__ Cout, const float* __restrict__ R,
    int M, int K, int epi)
{
    const int N = W_FR;
    int c  = blockIdx.z;
    int bm = blockIdx.y * 128;
    int bn = blockIdx.x * 128;
    A  += (size_t)c * M * K;
    BT += (size_t)c * N * K;
    float*  Cf = (float*)Cout + (size_t)c * M * N;
    __half* Ch = (__half*)Cout + (size_t)c * M * N;   // epi 3
    __half* Ct = (__half*)Cout + (size_t)c * N * M;   // epi 1 (transposed out)
    if (R) R += (size_t)c * M * N;

    extern __shared__ __align__(16) __half hsm[];
    uint32_t smb = smem_u32(hsm);

    int tid  = threadIdx.x;
    int warp = tid >> 5;
    int lane = tid & 31;
    int gid  = lane >> 2;
    int tig  = lane & 3;
    int wm   = warp >> 2;
    int wn   = warp & 3;

    // copy assignment: row = tid>>1, chunk = (tid&1)*16 halves, 2 cp16/matrix
    int cr = tid >> 1;
    int cc = (tid & 1) * 16;
    const __half* Ag = A  + (size_t)(bm + cr) * K + cc;
    const __half* Bg = BT + (size_t)(bn + cr) * K + cc;
    uint32_t sdst = (uint32_t)(cr * HP + cc) * 2;

    // ldmatrix per-lane offsets
    int lr = lane & 7;
    int lm = (lane >> 3) & 1;
    int lc = (lane >> 4) & 1;
    uint32_t aoff = (uint32_t)((wm * 64 + lr + lm * 8) * HP + lc * 8) * 2;
    uint32_t boff = (uint32_t)((wn * 32 + lr + lc * 8) * HP + lm * 8) * 2;

    const int NT = K / BK2;

    // prologue: stages 0..2
#pragma unroll
    for (int t = 0; t < NSTG - 1; t++) {
        uint32_t sA = smb + (uint32_t)(t * 2 * HG_MAT) * 2;
        uint32_t sB = sA + HG_MAT * 2;
        cp16s(sA + sdst,      Ag + (size_t)t * BK2);
        cp16s(sA + sdst + 16, Ag + (size_t)t * BK2 + 8);
        cp16s(sB + sdst,      Bg + (size_t)t * BK2);
        cp16s(sB + sdst + 16, Bg + (size_t)t * BK2 + 8);
        asm volatile("cp.async.commit_group;");
    }

    float acc[4][4][4];
#pragma unroll
    for (int i = 0; i < 4; i++)
#pragma unroll
        for (int j = 0; j < 4; j++)
#pragma unroll
            for (int q = 0; q < 4; q++) acc[i][j][q] = 0.f;

    for (int t = 0; t < NT; t++) {
        uint32_t sA = smb + (uint32_t)((t % NSTG) * 2 * HG_MAT) * 2;
        uint32_t sB = sA + HG_MAT * 2;
        asm volatile("cp.async.wait_group %0;" :: "n"(NSTG - 2));
        __syncthreads();

#pragma unroll
        for (int s = 0; s < 2; s++) {
            uint32_t bf[2][4];
            ldsm4(bf[0], sB + boff + (0 * 16 * HP + s * 16) * 2);
            ldsm4(bf[1], sB + boff + (1 * 16 * HP + s * 16) * 2);
#pragma unroll
            for (int mt = 0; mt < 4; mt++) {
                uint32_t af[4];
                ldsm4(af, sA + aoff + (mt * 16 * HP + s * 16) * 2);
                mma_f16(acc[mt][0], af, &bf[0][0]);
                mma_f16(acc[mt][1], af, &bf[0][2]);
                mma_f16(acc[mt][2], af, &bf[1][0]);
                mma_f16(acc[mt][3], af, &bf[1][2]);
            }
        }

        if (t + NSTG - 1 < NT) {
            int tn = t + NSTG - 1;
            uint32_t dA = smb + (uint32_t)((tn % NSTG) * 2 * HG_MAT) * 2;
            uint32_t dB = dA + HG_MAT * 2;
            cp16s(dA + sdst,      Ag + (size_t)tn * BK2);
            cp16s(dA + sdst + 16, Ag + (size_t)tn * BK2 + 8);
            cp16s(dB + sdst,      Bg + (size_t)tn * BK2);
            cp16s(dB + sdst + 16, Bg + (size_t)tn * BK2 + 8);
        }
        asm volatile("cp.async.commit_group;");
    }

    if (epi == 1) {
        // GELU + fp16 + transpose via smem, store Ct[n][M]
        asm volatile("cp.async.wait_group 0;");
        __syncthreads();
        __half* ts = hsm;                     // [128 n][136 m]
#pragma unroll
        for (int mt = 0; mt < 4; mt++)
#pragma unroll
            for (int nt = 0; nt < 4; nt++)
#pragma unroll
                for (int q = 0; q < 4; q++) {
                    int row = wm * 64 + mt * 16 + gid + (q >> 1) * 8;
                    int col = wn * 32 + nt * 8 + 2 * tig + (q & 1);
                    ts[col * 136 + row] = __float2half(gelu_exact(acc[mt][nt][q]));
                }
        __syncthreads();
#pragma unroll
        for (int pp = 0; pp < 8; pp++) {
            int nr  = pp * 16 + (tid >> 4);
            int c16 = (tid & 15) * 8;
            uint4 v = *(const uint4*)&ts[nr * 136 + c16];
            *(uint4*)&Ct[(size_t)(bn + nr) * M + bm + c16] = v;
        }
        return;
    }

#pragma unroll
    for (int mt = 0; mt < 4; mt++) {
#pragma unroll
        for (int nt = 0; nt < 4; nt++) {
            int row0 = bm + wm * 64 + mt * 16 + gid;
            int col  = bn + wn * 32 + nt * 8 + 2 * tig;
#pragma unroll
            for (int h = 0; h < 2; h++) {
                int row = row0 + h * 8;
                float2 v = make_float2(acc[mt][nt][h * 2], acc[mt][nt][h * 2 + 1]);
                size_t off = (size_t)row * N + col;
                if (epi == 3) {
                    *(__half2*)(Ch + off) = __floats2half2_rn(v.x, v.y);
                } else {
                    float2 rv = *(const float2*)(R + off);
                    v.x += rv.x; v.y += rv.y;
                    *(float2*)(Cf + off) = v;
                }
            }
        }
    }
}

// ---------------------------------------------------------------------------
// Flash attention, fp16 mma. Reads fp16 projection p[d][w]; writes output
// DIRECTLY to t1h fp16 transposed ([w][f] layout). Grid 256, 256 thr.
// ---------------------------------------------------------------------------
#define AQS 72
#define AVS 520
#define ATT_SMEM (512 * AQS * 2 + 64 * AVS * 2)   // 140,288 B

__global__ __launch_bounds__(256) void fattn_kernel(
    const __half* __restrict__ ph, const float* __restrict__ freqs,
    __half* __restrict__ t1)
{
    extern __shared__ __align__(16) char smraw[];
    __half* qk = (__half*)smraw;
    __half* vs = (__half*)(smraw + 512 * AQS * 2);

    int head = blockIdx.x >> 1;
    int qh   = blockIdx.x & 1;
    int c  = head >> 4;
    int hh = head & 15;
    const __half* slab = ph + ((size_t)c * F_DIM + (size_t)hh * D_HEAD) * W_FR;

    int tid = threadIdx.x;

#pragma unroll
    for (int rep = 0; rep < 2; rep++) {
        int w = tid + rep * 256;
        float fw = (float)w;
#pragma unroll
        for (int i = 0; i < 16; i++) {
            float e0 = __half2float(slab[(size_t)(2 * i) * W_FR + w]);
            float e1 = __half2float(slab[(size_t)(2 * i + 1) * W_FR + w]);
            float si, co;
            sincosf(fw * freqs[i], &si, &co);
            qk[w * AQS + 2 * i]     = __float2half(e0 * co - e1 * si);
            qk[w * AQS + 2 * i + 1] = __float2half(e1 * co + e0 * si);
            vs[(2 * i) * AVS + w]     = __float2half(e0);
            vs[(2 * i + 1) * AVS + w] = __float2half(e1);
        }
#pragma unroll
        for (int d = 32; d < 64; d++) {
            __half he = slab[(size_t)d * W_FR + w];
            qk[w * AQS + d] = he;
            vs[d * AVS + w] = he;
        }
    }
    __syncthreads();

    int warp = tid >> 5, lane = tid & 31, gid = lane >> 2, tig = lane & 3;
    int q0 = qh * 256 + warp * 32;
    const float scale = 0.03125f;

    uint32_t qf[2][4][4];
#pragma unroll
    for (int mt = 0; mt < 2; mt++) {
        int qr = q0 + mt * 16 + gid;
#pragma unroll
        for (int ks = 0; ks < 4; ks++) {
            int kb = 16 * ks + 2 * tig;
            qf[mt][ks][0] = *(const uint32_t*)&qk[qr * AQS + kb];
            qf[mt][ks][1] = *(const uint32_t*)&qk[(qr + 8) * AQS + kb];
            qf[mt][ks][2] = *(const uint32_t*)&qk[qr * AQS + kb + 8];
            qf[mt][ks][3] = *(const uint32_t*)&qk[(qr + 8) * AQS + kb + 8];
        }
    }

    float oacc[2][8][4];
#pragma unroll
    for (int mt = 0; mt < 2; mt++)
#pragma unroll
        for (int nt = 0; nt < 8; nt++)
#pragma unroll
            for (int q = 0; q < 4; q++) oacc[mt][nt][q] = 0.f;
    float mrow[2][2] = { {-1e30f, -1e30f}, {-1e30f, -1e30f} };
    float lrow[2][2] = { {0.f, 0.f}, {0.f, 0.f} };

    for (int ch = 0; ch < 8; ch++) {
        int cb = ch * 64;
        float sacc[2][8][4];
#pragma unroll
        for (int mt = 0; mt < 2; mt++)
#pragma unroll
            for (int nt = 0; nt < 8; nt++)
#pragma unroll
                for (int q = 0; q < 4; q++) sacc[mt][nt][q] = 0.f;

#pragma unroll
        for (int ks = 0; ks < 4; ks++) {
#pragma unroll
            for (int nt = 0; nt < 8; nt++) {
                int kr = cb + nt * 8 + gid;
                uint32_t bf[2];
                int kb = 16 * ks + 2 * tig;
                bf[0] = *(const uint32_t*)&qk[kr * AQS + kb];
                bf[1] = *(const uint32_t*)&qk[kr * AQS + kb + 8];
                mma_f16(sacc[0][nt], qf[0][ks], bf);
                mma_f16(sacc[1][nt], qf[1][ks], bf);
            }
        }

#pragma unroll
        for (int mt = 0; mt < 2; mt++) {
#pragma unroll
            for (int h = 0; h < 2; h++) {
                float mx = -1e30f;
#pragma unroll
                for (int nt = 0; nt < 8; nt++) {
                    mx = fmaxf(mx, sacc[mt][nt][h * 2]);
                    mx = fmaxf(mx, sacc[mt][nt][h * 2 + 1]);
                }
                mx *= scale;
                mx = fmaxf(mx, __shfl_xor_sync(0xFFFFFFFF, mx, 1));
                mx = fmaxf(mx, __shfl_xor_sync(0xFFFFFFFF, mx, 2));
                float newm = fmaxf(mrow[mt][h], mx);
                float scl  = __expf(mrow[mt][h] - newm);
                float rsum = 0.f;
#pragma unroll
                for (int nt = 0; nt < 8; nt++) {
                    float e0 = __expf(sacc[mt][nt][h * 2] * scale - newm);
                    float e1 = __expf(sacc[mt][nt][h * 2 + 1] * scale - newm);
                    sacc[mt][nt][h * 2]     = e0;
                    sacc[mt][nt][h * 2 + 1] = e1;
                    rsum += e0 + e1;
                }
                rsum += __shfl_xor_sync(0xFFFFFFFF, rsum, 1);
                rsum += __shfl_xor_sync(0xFFFFFFFF, rsum, 2);
                lrow[mt][h] = lrow[mt][h] * scl + rsum;
                mrow[mt][h] = newm;
#pragma unroll
                for (int nt = 0; nt < 8; nt++) {
                    oacc[mt][nt][h * 2]     *= scl;
                    oacc[mt][nt][h * 2 + 1] *= scl;
                }
            }
        }

#pragma unroll
        for (int ks = 0; ks < 4; ks++) {
            uint32_t pf[2][4];
#pragma unroll
            for (int mt = 0; mt < 2; mt++) {
                __half2 h0 = __floats2half2_rn(sacc[mt][2 * ks][0],     sacc[mt][2 * ks][1]);
                __half2 h1 = __floats2half2_rn(sacc[mt][2 * ks][2],     sacc[mt][2 * ks][3]);
                __half2 h2 = __floats2half2_rn(sacc[mt][2 * ks + 1][0], sacc[mt][2 * ks + 1][1]);
                __half2 h3 = __floats2half2_rn(sacc[mt][2 * ks + 1][2], sacc[mt][2 * ks + 1][3]);
                pf[mt][0] = *(uint32_t*)&h0;
                pf[mt][1] = *(uint32_t*)&h1;
                pf[mt][2] = *(uint32_t*)&h2;
                pf[mt][3] = *(uint32_t*)&h3;
            }
#pragma unroll
            for (int dnt = 0; dnt < 8; dnt++) {
                int vr = dnt * 8 + gid;
                uint32_t vf[2];
                int kcol = cb + 16 * ks + 2 * tig;
                vf[0] = *(const uint32_t*)&vs[vr * AVS + kcol];
                vf[1] = *(const uint32_t*)&vs[vr * AVS + kcol + 8];
                mma_f16(oacc[0][dnt], pf[0], vf);
                mma_f16(oacc[1][dnt], pf[1], vf);
            }
        }
    }

    // direct fp16 transposed output into t1h[w][f]
    __half* tout = t1 + ((size_t)c * W_FR + qh * 256) * F_DIM + hh * D_HEAD;
#pragma unroll
    for (int mt = 0; mt < 2; mt++)
#pragma unroll
        for (int dnt = 0; dnt < 8; dnt++)
#pragma unroll
            for (int h = 0; h < 2; h++) {
                int row = warp * 32 + mt * 16 + gid + h * 8;
                int d2  = dnt * 8 + 2 * tig;
                float li = 1.f / lrow[mt][h];
                *(__half2*)(tout + (size_t)row * F_DIM + d2) =
                    __floats2half2_rn(oacc[mt][dnt][h * 2] * li,
                                      oacc[mt][dnt][h * 2 + 1] * li);
            }
}

// ---------------------------------------------------------------------------
// Launch
// ---------------------------------------------------------------------------
extern "C" void kernel_launch(void* const* d_in, const int* in_sizes, int n_in,
                              void* d_out, int out_size)
{
    (void)in_sizes; (void)n_in; (void)out_size;
    const float* x  = (const float*)d_in[0];
    const float* g1 = (const float*)d_in[1];
    const float* b1 = (const float*)d_in[2];
    const float* wq = (const float*)d_in[3];
    const float* wo = (const float*)d_in[4];
    const float* fr = (const float*)d_in[5];
    const float* g2 = (const float*)d_in[6];
    const float* b2 = (const float*)d_in[7];
    const float* w1 = (const float*)d_in[8];
    const float* w2 = (const float*)d_in[9];
    float* out = (float*)d_out;

    __half *ph, *wqh, *woh, *w1h, *w2h, *t1h, *t2h;
    cudaGetSymbolAddress((void**)&ph,  g_ph);
    cudaGetSymbolAddress((void**)&wqh, g_wqh);
    cudaGetSymbolAddress((void**)&woh, g_woh);
    cudaGetSymbolAddress((void**)&w1h, g_w1h);
    cudaGetSymbolAddress((void**)&w2h, g_w2h);
    cudaGetSymbolAddress((void**)&t1h, g_t1h);
    cudaGetSymbolAddress((void**)&t2h, g_t2h);

    cudaFuncSetAttribute(fattn_kernel,
                         cudaFuncAttributeMaxDynamicSharedMemorySize, ATT_SMEM);
    cudaFuncSetAttribute(hgemm_kernel,
                         cudaFuncAttributeMaxDynamicSharedMemorySize, HG_SMEM);

    const size_t nw  = (size_t)C_CH * F_DIM * F_DIM;
    const size_t nw1 = (size_t)C_CH * F4 * F_DIM;

    // weight conversions (fp32 -> fp16)
    f2h_kernel<<<(int)(nw  / 4 / 256), 256>>>(wq, wqh, nw);
    f2h_kernel<<<(int)(nw  / 4 / 256), 256>>>(wo, woh, nw);
    f2h_kernel<<<(int)(nw1 / 4 / 256), 256>>>(w1, w1h, nw1);
    f2h_kernel<<<(int)(nw1 / 4 / 256), 256>>>(w2, w2h, nw1);

    // t1h = (half) norm(x)^T
    norm_t_kernel<<<dim3(8, 16), 256>>>(x, g1, b1, t1h);
    // ph (fp16) = w_q @ z
    hgemm_kernel<<<dim3(4, 8, 8), 256, HG_SMEM>>>(wqh, t1h, ph, nullptr, F_DIM, F_DIM, 3);
    // t1h = attention(ph)^T (fp16, direct)
    fattn_kernel<<<256, 256, ATT_SMEM>>>(ph, fr, t1h);
    // out = x + w_o @ o
    hgemm_kernel<<<dim3(4, 8, 8), 256, HG_SMEM>>>(woh, t1h, out, x, F_DIM, F_DIM, 2);
    // t1h = (half) norm(out)^T
    norm_t_kernel<<<dim3(8, 16), 256>>>(out, g2, b2, t1h);
    // t2h = (gelu(w1 @ z))^T  (fp16, in-epilogue transpose)
    hgemm_kernel<<<dim3(4, 32, 8), 256, HG_SMEM>>>(w1h, t1h, t2h, nullptr, F4, F_DIM, 1);
    // out = out + w2 @ h
    hgemm_kernel<<<dim3(4, 8, 8), 256, HG_SMEM>>>(w2h, t2h, out, out, F_DIM, F4, 2);
}